// round 7
// baseline (speedup 1.0000x reference)
#include <cuda_runtime.h>
#include <math.h>

#define NB 512
#define ND 512
#define EPSF 1e-6f
#define HEPS (0.5f*1e-6f)

typedef unsigned long long u64t;

// ---------------- f32x2 packed helpers (sm_100a) ----------------
__device__ __forceinline__ u64t pk2(float lo, float hi){ u64t r; asm("mov.b64 %0, {%1,%2};" : "=l"(r) : "f"(lo), "f"(hi)); return r; }
__device__ __forceinline__ void upk2(u64t v, float&lo, float&hi){ asm("mov.b64 {%0,%1}, %2;" : "=f"(lo), "=f"(hi) : "l"(v)); }
__device__ __forceinline__ u64t fma2_(u64t a,u64t b,u64t c){ u64t d; asm("fma.rn.f32x2 %0,%1,%2,%3;" : "=l"(d) : "l"(a),"l"(b),"l"(c)); return d; }
__device__ __forceinline__ u64t mul2_(u64t a,u64t b){ u64t d; asm("mul.rn.f32x2 %0,%1,%2;" : "=l"(d) : "l"(a),"l"(b)); return d; }
__device__ __forceinline__ u64t add2_(u64t a,u64t b){ u64t d; asm("add.rn.f32x2 %0,%1,%2;" : "=l"(d) : "l"(a),"l"(b)); return d; }
__device__ __forceinline__ float rcpa(float x){ float r; asm("rcp.approx.f32 %0, %1;" : "=f"(r) : "f"(x)); return r; }
__device__ __forceinline__ float lg2a(float x){ float r; asm("lg2.approx.f32 %0, %1;" : "=f"(r) : "f"(x)); return r; }

// ---------------- scratch ----------------
__device__ float g_n1[NB * ND];    // normalized mu1, [i][d]
__device__ float g_h1[NB * ND];    // 0.5*sigma1 + HEPS, [i][d]
__device__ float g_n2t[NB * ND];   // NEGATED normalized mu2, TRANSPOSED [d][j]
__device__ float g_h2t[NB * ND];   // 0.5*sigma2 + HEPS, TRANSPOSED [d][j]
__device__ float g_sim[NB * NB];
__device__ float g_sim2[NB * NB];
__device__ float g_ld1[NB], g_ld2[NB];
__device__ float g_ms1[NB], g_ms2[NB];
__device__ float g_inv2[NB];       // negated inv-norm for mu2 rows
__device__ float g_lse_row[NB], g_diagl[NB], g_u[NB];
__device__ float g_cm[8 * NB], g_cs[8 * NB];
__device__ int   g_ctr;

// ---------------- reduction helpers ----------------
__device__ __forceinline__ float wsum(float v) {
#pragma unroll
    for (int o = 16; o; o >>= 1) v += __shfl_down_sync(0xffffffffu, v, o);
    return v;
}
__device__ __forceinline__ float wmax(float v) {
#pragma unroll
    for (int o = 16; o; o >>= 1) v = fmaxf(v, __shfl_down_sync(0xffffffffu, v, o));
    return v;
}

// ---------------- kernel 1: per-row reductions; side-1 arrays written here ----------------
__global__ void prep_kernel(const float* __restrict__ mu1, const float* __restrict__ s1,
                            const float* __restrict__ mu2, const float* __restrict__ s2)
{
    __shared__ float sh[3][8];
    __shared__ float s_inv;
    const int row = blockIdx.x;
    const bool first = row < NB;
    const int r = first ? row : row - NB;
    const float* mu = (first ? mu1 : mu2) + r * ND;
    const float* sg = (first ? s1 : s2) + r * ND;
    const int t = threadIdx.x;

    if (row == 0 && t == 0) g_ctr = 0;   // reset last-block counter each launch

    float ssq = 0.f, lsum = 0.f, msum = 0.f;
    for (int c = t; c < ND; c += 256) {
        float x = mu[c];
        ssq += x * x;
        float sv = sg[c];
        lsum += __logf(sv + EPSF);
        msum += sv;
        if (first) g_h1[r * ND + c] = fmaf(0.5f, sv, HEPS);
    }
    ssq = wsum(ssq); lsum = wsum(lsum); msum = wsum(msum);
    const int lane = t & 31, w = t >> 5;
    if (!lane) { sh[0][w] = ssq; sh[1][w] = lsum; sh[2][w] = msum; }
    __syncthreads();
    if (t == 0) {
        float a = 0.f, b = 0.f, c2 = 0.f;
        for (int k = 0; k < 8; k++) { a += sh[0][k]; b += sh[1][k]; c2 += sh[2][k]; }
        float inv = 1.0f / fmaxf(sqrtf(a), 1e-12f);
        s_inv = inv;
        (first ? g_ld1 : g_ld2)[r] = b;
        (first ? g_ms1 : g_ms2)[r] = c2 * (1.0f / ND);
        if (!first) g_inv2[r] = -inv;          // negate n2 here
    }
    __syncthreads();
    if (first) {
        const float inv = s_inv;
        for (int c = t; c < ND; c += 256) g_n1[r * ND + c] = mu[c] * inv;
    }
}

// ---------------- kernel 2: transpose + scale side-2 arrays ----------------
// writes g_n2t[d][j] = -inv2[j]*mu2[j][d],  g_h2t[d][j] = 0.5*s2[j][d]+HEPS
__global__ void tscale_kernel(const float* __restrict__ mu2, const float* __restrict__ s2)
{
    __shared__ float tn[32][33], th[32][33];
    const int bx = blockIdx.x * 32;   // d origin
    const int by = blockIdx.y * 32;   // j origin
    const int tx = threadIdx.x, ty = threadIdx.y;   // 32 x 8
#pragma unroll
    for (int k = 0; k < 4; k++) {
        const int j = by + ty + k * 8;
        const float iv = g_inv2[j];
        tn[ty + k * 8][tx] = mu2[j * ND + bx + tx] * iv;
        th[ty + k * 8][tx] = fmaf(0.5f, s2[j * ND + bx + tx], HEPS);
    }
    __syncthreads();
#pragma unroll
    for (int k = 0; k < 4; k++) {
        const int d = bx + ty + k * 8;
        g_n2t[d * NB + by + tx] = tn[tx][ty + k * 8];
        g_h2t[d * NB + by + tx] = th[tx][ty + k * 8];
    }
}

// ---------------- kernel 3: Bhattacharyya O(B^2 D) pass ----------------
// 32x32 tile, 128 threads, microtile 4i x 2j (packed f32x2 on j).
// cp.async double-buffered pipeline; all four smem tiles loaded with straight
// 16B async copies (B-side pre-transposed in global), conflict-free LDS.
__global__ void __launch_bounds__(128) bd_kernel()
{
    __shared__ __align__(16) float sbuf[2][4][32][36];

    const int bi = blockIdx.y * 32, bj = blockIdx.x * 32;
    const int t = threadIdx.x;
    const int tx = t & 15, ty = t >> 4;
    const int i0 = 4 * ty, j0 = 2 * tx;

    u64t t1a[4], d2a[4], lda[4];
#pragma unroll
    for (int x = 0; x < 4; x++) { t1a[x] = 0ull; d2a[x] = 0ull; lda[x] = 0ull; }

    const float* b0 = g_n1  + bi * ND;
    const float* b1 = g_h1  + bi * ND;
    const float* b2 = g_n2t + bj;
    const float* b3 = g_h2t + bj;

    // issue one chunk's loads into buffer bsel: 8 x 16B cp.async per thread
#define ISSUE_CHUNK(dc, bsel) do {                                             \
        _Pragma("unroll")                                                      \
        for (int k = 0; k < 8; k++) {                                          \
            const int arr = k >> 1;                                            \
            const int rem = ((k & 1) << 7) + t;                                \
            const int row = rem >> 3, seg = rem & 7;                           \
            const float* src;                                                  \
            if (arr == 0)      src = b0 + row * ND + (dc) + seg * 4;           \
            else if (arr == 1) src = b1 + row * ND + (dc) + seg * 4;           \
            else if (arr == 2) src = b2 + ((dc) + row) * ND + seg * 4;         \
            else               src = b3 + ((dc) + row) * ND + seg * 4;         \
            unsigned dst = (unsigned)__cvta_generic_to_shared(                 \
                &sbuf[bsel][arr][row][seg * 4]);                               \
            asm volatile("cp.async.cg.shared.global [%0], [%1], 16;"           \
                         :: "r"(dst), "l"(src));                               \
        }                                                                      \
        asm volatile("cp.async.commit_group;" ::: "memory");                   \
    } while (0)

    ISSUE_CHUNK(0, 0);

    for (int c = 0; c < 16; c++) {
        const int b = c & 1;
        if (c < 15) {
            ISSUE_CHUNK((c + 1) * 32, b ^ 1);
            asm volatile("cp.async.wait_group 1;" ::: "memory");
        } else {
            asm volatile("cp.async.wait_group 0;" ::: "memory");
        }
        __syncthreads();

        const float (*An)[36] = sbuf[b][0];
        const float (*Ap)[36] = sbuf[b][1];
        const float (*Bn)[36] = sbuf[b][2];
        const float (*Bq)[36] = sbuf[b][3];

#pragma unroll 2
        for (int dg = 0; dg < 32; dg += 4) {
            u64t bn[4], bq[4];
#pragma unroll
            for (int dd = 0; dd < 4; dd++) {
                bn[dd] = *(const u64t*)&Bn[dg + dd][j0];
                bq[dd] = *(const u64t*)&Bq[dg + dd][j0];
            }
#pragma unroll
            for (int x = 0; x < 4; x++) {
                const float4 av = *(const float4*)&An[i0 + x][dg];
                const float4 pv = *(const float4*)&Ap[i0 + x][dg];
                const u64t s0  = add2_(pk2(pv.x, pv.x), bq[0]);
                const u64t s1_ = add2_(pk2(pv.y, pv.y), bq[1]);
                const u64t s2_ = add2_(pk2(pv.z, pv.z), bq[2]);
                const u64t s3_ = add2_(pk2(pv.w, pv.w), bq[3]);
                const u64t df0 = add2_(pk2(av.x, av.x), bn[0]);   // a - b (b negated)
                const u64t df1 = add2_(pk2(av.y, av.y), bn[1]);
                const u64t df2 = add2_(pk2(av.z, av.z), bn[2]);
                const u64t df3 = add2_(pk2(av.w, av.w), bn[3]);
                const u64t sq0 = mul2_(df0, df0);
                const u64t sq1 = mul2_(df1, df1);
                const u64t sq2 = mul2_(df2, df2);
                const u64t sq3 = mul2_(df3, df3);
                d2a[x] = add2_(d2a[x], add2_(add2_(sq0, sq1), add2_(sq2, sq3)));
                // batched log + Montgomery batch inversion over 4 d's
                const u64t p01  = mul2_(s0, s1_);
                const u64t p012 = mul2_(p01, s2_);
                const u64t Pp   = mul2_(p012, s3_);
                float Pl, Ph; upk2(Pp, Pl, Ph);
                lda[x] = add2_(lda[x], pk2(lg2a(Pl), lg2a(Ph)));
                const u64t r2   = pk2(rcpa(Pl), rcpa(Ph));
                const u64t inv3 = mul2_(r2, p012);
                const u64t r3   = mul2_(r2, s3_);
                const u64t inv2 = mul2_(r3, p01);
                const u64t r23  = mul2_(r3, s2_);
                const u64t inv1 = mul2_(r23, s0);
                const u64t inv0 = mul2_(r23, s1_);
                t1a[x] = fma2_(sq0, inv0, t1a[x]);
                t1a[x] = fma2_(sq1, inv1, t1a[x]);
                t1a[x] = fma2_(sq2, inv2, t1a[x]);
                t1a[x] = fma2_(sq3, inv3, t1a[x]);
            }
        }
        __syncthreads();
    }
#undef ISSUE_CHUNK

    // epilogue: sim = exp(-bd/D), sim2 = exp(-||n1-n2||^2)
    const int j = bj + j0;
    const float ld2A = g_ld2[j], ld2B = g_ld2[j + 1];
#pragma unroll
    for (int x = 0; x < 4; x++) {
        const int i = bi + i0 + x;
        const float ld1v = g_ld1[i];
        float tA, tB, dA, dB, lA, lB;
        upk2(t1a[x], tA, tB);
        upk2(d2a[x], dA, dB);
        upk2(lda[x], lA, lB);
        const float t2A = lA * (float)M_LN2 - 0.5f * (ld1v + ld2A);
        const float t2B = lB * (float)M_LN2 - 0.5f * (ld1v + ld2B);
        const float bdA = fmaf(0.125f, tA, 0.5f * t2A);
        const float bdB = fmaf(0.125f, tB, 0.5f * t2B);
        *(float2*)&g_sim[i * NB + j]  = make_float2(__expf(-bdA * (1.0f / ND)),
                                                    __expf(-bdB * (1.0f / ND)));
        *(float2*)&g_sim2[i * NB + j] = make_float2(__expf(-dA), __expf(-dB));
    }
}

// ---------------- kernel 4: row LSE + col partials + fused final (last block) ----------------
__global__ void rowcol_kernel(const float* __restrict__ lsp, float* __restrict__ out)
{
    const float scale = lsp[0];
    const int t = threadIdx.x;
    const int lane = t & 31, w = t >> 5;

    if (blockIdx.x < NB) {
        __shared__ float shm[8], shm2[8], shs[8];
        __shared__ float s_diag, s_diag2, s_M, s_M2;
        const int i = blockIdx.x;
        const float* simr = g_sim + i * NB;
        const float* sim2r = g_sim2 + i * NB;

        const float l0 = scale * simr[t], l1 = scale * simr[t + 256];
        const float v0 = sim2r[t],        v1 = sim2r[t + 256];
        float m = fmaxf(l0, l1);
        float m2 = -1.0f;
        if (t == i)       { s_diag = l0; s_diag2 = v0; } else m2 = v0;
        if (t + 256 == i) { s_diag = l1; s_diag2 = v1; } else m2 = fmaxf(m2, v1);

        m = wmax(m); m2 = wmax(m2);
        if (!lane) { shm[w] = m; shm2[w] = m2; }
        __syncthreads();
        if (t == 0) {
            float M = shm[0], M2 = shm2[0];
            for (int k = 1; k < 8; k++) { M = fmaxf(M, shm[k]); M2 = fmaxf(M2, shm2[k]); }
            s_M = M; s_M2 = M2;
        }
        __syncthreads();
        const float M = s_M;
        float su = __expf(l0 - M) + __expf(l1 - M);
        su = wsum(su);
        if (!lane) shs[w] = su;
        __syncthreads();
        if (t == 0) {
            float S = 0.f;
            for (int k = 0; k < 8; k++) S += shs[k];
            g_lse_row[i] = M + __logf(S);
            g_diagl[i]   = s_diag;
            g_u[i]       = __expf(-s_diag2 / s_M2);
        }
    } else {
        __shared__ float sm[8][32], ssp[8][32];
        const int bid = blockIdx.x - NB;
        const int jg = bid & 15, rg = bid >> 4;      // 16 col-groups x 8 row-stripes
        const int x = t & 31, y = t >> 5;
        const int j = jg * 32 + x;
        const int r0 = rg * 64 + y * 8;
        float m = -1e30f, s = 0.0f;
#pragma unroll
        for (int k = 0; k < 8; k++) {
            const float l = scale * g_sim[(r0 + k) * NB + j];
            const float nm = fmaxf(m, l);
            s = s * __expf(m - nm) + __expf(l - nm);
            m = nm;
        }
        sm[y][x] = m; ssp[y][x] = s;
        __syncthreads();
        if (y == 0) {
            float M = m;
#pragma unroll
            for (int k = 1; k < 8; k++) M = fmaxf(M, sm[k][x]);
            float S = 0.f;
#pragma unroll
            for (int k = 0; k < 8; k++) S += ssp[k][x] * __expf(sm[k][x] - M);
            g_cm[rg * NB + j] = M;
            g_cs[rg * NB + j] = S;
        }
    }

    // ---- last-block final reduction ----
    __shared__ int s_last;
    __threadfence();
    __syncthreads();
    if (t == 0) s_last = (atomicAdd(&g_ctr, 1) == NB + 128 - 1);
    __syncthreads();
    if (!s_last) return;
    __threadfence();

    __shared__ float fsh[6][8];
    float acc[6] = {0.f, 0.f, 0.f, 0.f, 0.f, 0.f};
    for (int idx = t; idx < NB; idx += 256) {
        float M = -1e30f;
#pragma unroll
        for (int k = 0; k < 8; k++) M = fmaxf(M, g_cm[k * NB + idx]);
        float S = 0.f;
#pragma unroll
        for (int k = 0; k < 8; k++) S += g_cs[k * NB + idx] * __expf(g_cm[k * NB + idx] - M);
        const float lse_col = M + __logf(S);
        const float diag = g_diagl[idx];
        const float u = g_u[idx];
        const float as = 0.5f * (g_ms1[idx] + g_ms2[idx]);
        acc[0] += g_lse_row[idx] - diag;
        acc[1] += lse_col - diag;
        acc[2] += u;
        acc[3] += u * u;
        acc[4] += as * as;
        acc[5] += u * as;
    }
#pragma unroll
    for (int k = 0; k < 6; k++) {
        const float r = wsum(acc[k]);
        if (!lane) fsh[k][w] = r;
    }
    __syncthreads();
    if (t == 0) {
        float s[6];
        for (int k = 0; k < 6; k++) {
            float a = 0.f;
            for (int q = 0; q < 8; q++) a += fsh[k][q];
            s[k] = a;
        }
        const float loss_pro = 0.5f * ((s[0] + s[1]) * (1.0f / NB));
        const float cosv = s[5] / (fmaxf(sqrtf(s[3]), 1e-12f) * fmaxf(sqrtf(s[4]), 1e-12f));
        out[0] = loss_pro;
        out[1] = 2.4f * (1.0f - cosv);
        out[2] = 0.5f * (s[2] * (1.0f / NB));
    }
}

// ---------------- launch ----------------
extern "C" void kernel_launch(void* const* d_in, const int* in_sizes, int n_in,
                              void* d_out, int out_size)
{
    const float* mu1 = (const float*)d_in[0];
    const float* s1  = (const float*)d_in[1];
    const float* mu2 = (const float*)d_in[2];
    const float* s2  = (const float*)d_in[3];
    const float* ls  = (const float*)d_in[4];
    float* out = (float*)d_out;

    prep_kernel<<<2 * NB, 256>>>(mu1, s1, mu2, s2);
    tscale_kernel<<<dim3(16, 16), dim3(32, 8)>>>(mu2, s2);
    bd_kernel<<<dim3(NB / 32, NB / 32), 128>>>();
    rowcol_kernel<<<NB + 128, 256>>>(ls, out);
}

// round 8
// speedup vs baseline: 1.1120x; 1.1120x over previous
#include <cuda_runtime.h>
#include <math.h>

#define NB 512
#define ND 512
#define EPSF 1e-6f
#define HEPS (0.5f*1e-6f)

typedef unsigned long long u64t;

// ---------------- f32x2 packed helpers (sm_100a) ----------------
__device__ __forceinline__ u64t pk2(float lo, float hi){ u64t r; asm("mov.b64 %0, {%1,%2};" : "=l"(r) : "f"(lo), "f"(hi)); return r; }
__device__ __forceinline__ void upk2(u64t v, float&lo, float&hi){ asm("mov.b64 {%0,%1}, %2;" : "=f"(lo), "=f"(hi) : "l"(v)); }
__device__ __forceinline__ u64t fma2_(u64t a,u64t b,u64t c){ u64t d; asm("fma.rn.f32x2 %0,%1,%2,%3;" : "=l"(d) : "l"(a),"l"(b),"l"(c)); return d; }
__device__ __forceinline__ u64t mul2_(u64t a,u64t b){ u64t d; asm("mul.rn.f32x2 %0,%1,%2;" : "=l"(d) : "l"(a),"l"(b)); return d; }
__device__ __forceinline__ u64t add2_(u64t a,u64t b){ u64t d; asm("add.rn.f32x2 %0,%1,%2;" : "=l"(d) : "l"(a),"l"(b)); return d; }
__device__ __forceinline__ float rcpa(float x){ float r; asm("rcp.approx.f32 %0, %1;" : "=f"(r) : "f"(x)); return r; }
__device__ __forceinline__ float lg2a(float x){ float r; asm("lg2.approx.f32 %0, %1;" : "=f"(r) : "f"(x)); return r; }

// ---------------- scratch ----------------
__device__ float g_n1[NB * ND];    // normalized mu1, [i][d]
__device__ float g_h1[NB * ND];    // 0.5*sigma1 + HEPS, [i][d]
__device__ float g_n2t[NB * ND];   // NEGATED normalized mu2, TRANSPOSED [d][j]
__device__ float g_h2t[NB * ND];   // 0.5*sigma2 + HEPS, TRANSPOSED [d][j]
__device__ float g_sim[NB * NB];
__device__ float g_sim2[NB * NB];
__device__ float g_ld1[NB], g_ld2[NB];
__device__ float g_ms1[NB], g_ms2[NB];
__device__ float g_inv2[NB];       // negated inv-norm for mu2 rows
__device__ float g_lse_row[NB], g_diagl[NB], g_u[NB];
__device__ float g_cm[8 * NB], g_cs[8 * NB];
__device__ int   g_ctr;

// ---------------- reduction helpers ----------------
__device__ __forceinline__ float wsum(float v) {
#pragma unroll
    for (int o = 16; o; o >>= 1) v += __shfl_down_sync(0xffffffffu, v, o);
    return v;
}
__device__ __forceinline__ float wmax(float v) {
#pragma unroll
    for (int o = 16; o; o >>= 1) v = fmaxf(v, __shfl_down_sync(0xffffffffu, v, o));
    return v;
}

// ---------------- kernel 1: per-row reductions; side-1 arrays written here ----------------
__global__ void prep_kernel(const float* __restrict__ mu1, const float* __restrict__ s1,
                            const float* __restrict__ mu2, const float* __restrict__ s2)
{
    __shared__ float sh[3][8];
    __shared__ float s_inv;
    const int row = blockIdx.x;
    const bool first = row < NB;
    const int r = first ? row : row - NB;
    const float* mu = (first ? mu1 : mu2) + r * ND;
    const float* sg = (first ? s1 : s2) + r * ND;
    const int t = threadIdx.x;

    if (row == 0 && t == 0) g_ctr = 0;   // reset last-block counter each launch

    float ssq = 0.f, lsum = 0.f, msum = 0.f;
    for (int c = t; c < ND; c += 256) {
        float x = mu[c];
        ssq += x * x;
        float sv = sg[c];
        lsum += __logf(sv + EPSF);
        msum += sv;
        if (first) g_h1[r * ND + c] = fmaf(0.5f, sv, HEPS);
    }
    ssq = wsum(ssq); lsum = wsum(lsum); msum = wsum(msum);
    const int lane = t & 31, w = t >> 5;
    if (!lane) { sh[0][w] = ssq; sh[1][w] = lsum; sh[2][w] = msum; }
    __syncthreads();
    if (t == 0) {
        float a = 0.f, b = 0.f, c2 = 0.f;
        for (int k = 0; k < 8; k++) { a += sh[0][k]; b += sh[1][k]; c2 += sh[2][k]; }
        float inv = 1.0f / fmaxf(sqrtf(a), 1e-12f);
        s_inv = inv;
        (first ? g_ld1 : g_ld2)[r] = b;
        (first ? g_ms1 : g_ms2)[r] = c2 * (1.0f / ND);
        if (!first) g_inv2[r] = -inv;          // negate n2 here
    }
    __syncthreads();
    if (first) {
        const float inv = s_inv;
        for (int c = t; c < ND; c += 256) g_n1[r * ND + c] = mu[c] * inv;
    }
}

// ---------------- kernel 2: transpose + scale side-2 arrays ----------------
__global__ void tscale_kernel(const float* __restrict__ mu2, const float* __restrict__ s2)
{
    __shared__ float tn[32][33], th[32][33];
    const int bx = blockIdx.x * 32;   // d origin
    const int by = blockIdx.y * 32;   // j origin
    const int tx = threadIdx.x, ty = threadIdx.y;   // 32 x 8
#pragma unroll
    for (int k = 0; k < 4; k++) {
        const int j = by + ty + k * 8;
        const float iv = g_inv2[j];
        tn[ty + k * 8][tx] = mu2[j * ND + bx + tx] * iv;
        th[ty + k * 8][tx] = fmaf(0.5f, s2[j * ND + bx + tx], HEPS);
    }
    __syncthreads();
#pragma unroll
    for (int k = 0; k < 4; k++) {
        const int d = bx + ty + k * 8;
        g_n2t[d * NB + by + tx] = tn[tx][ty + k * 8];
        g_h2t[d * NB + by + tx] = th[tx][ty + k * 8];
    }
}

// ---------------- kernel 3: Bhattacharyya O(B^2 D) pass ----------------
// 32x32 tile, 256 threads = 2 groups of 128 splitting D (warps 0-3 / 4-7, so
// every SMSP hosts a warp of each group). Each group runs a private cp.async
// double-buffered pipeline over 16-d chunks with its own named barrier.
#define SA_STRIDE 20   // 32 rows x 20 floats (80B = 5x16B: cp.async-aligned, LDS conflict-free)

__global__ void __launch_bounds__(256, 2) bd_kernel()
{
    __shared__ __align__(16) float sA[2][2][2][32 * SA_STRIDE];  // [grp][buf][n/h][i*20+d]
    __shared__ __align__(16) float sB[2][2][2][16 * 32];         // [grp][buf][n/h][d*32+j]

    const int bi = blockIdx.y * 32, bj = blockIdx.x * 32;
    const int tid = threadIdx.x;
    const int g  = tid >> 7;          // group id (warps 0-3 vs 4-7)
    const int t  = tid & 127;
    const int tx = t & 15, ty = t >> 4;
    const int i0 = 4 * ty, j0 = 2 * tx;

    u64t t1a[4], d2a[4], lda[4];
#pragma unroll
    for (int x = 0; x < 4; x++) { t1a[x] = 0ull; d2a[x] = 0ull; lda[x] = 0ull; }

    // per-thread load assignments (1 x 16B per array per chunk)
    const int arow = t >> 2, aseg = t & 3;    // A: 32 rows x 4 segs of 4 floats
    const int brow = t >> 3, bseg = t & 7;    // B: 16 rows x 8 segs
    const float* a0src = g_n1  + (bi + arow) * ND + aseg * 4;
    const float* a1src = g_h1  + (bi + arow) * ND + aseg * 4;
    const float* b0src = g_n2t + brow * NB + bj + bseg * 4;
    const float* b1src = g_h2t + brow * NB + bj + bseg * 4;

#define ISSUE_CHUNK(dc, bsel) do {                                                     \
        unsigned da0 = (unsigned)__cvta_generic_to_shared(                             \
            &sA[g][bsel][0][arow * SA_STRIDE + aseg * 4]);                             \
        unsigned da1 = (unsigned)__cvta_generic_to_shared(                             \
            &sA[g][bsel][1][arow * SA_STRIDE + aseg * 4]);                             \
        unsigned db0 = (unsigned)__cvta_generic_to_shared(                             \
            &sB[g][bsel][0][brow * 32 + bseg * 4]);                                    \
        unsigned db1 = (unsigned)__cvta_generic_to_shared(                             \
            &sB[g][bsel][1][brow * 32 + bseg * 4]);                                    \
        asm volatile("cp.async.cg.shared.global [%0], [%1], 16;" :: "r"(da0), "l"(a0src + (dc))); \
        asm volatile("cp.async.cg.shared.global [%0], [%1], 16;" :: "r"(da1), "l"(a1src + (dc))); \
        asm volatile("cp.async.cg.shared.global [%0], [%1], 16;" :: "r"(db0), "l"(b0src + (size_t)(dc) * NB)); \
        asm volatile("cp.async.cg.shared.global [%0], [%1], 16;" :: "r"(db1), "l"(b1src + (size_t)(dc) * NB)); \
        asm volatile("cp.async.commit_group;" ::: "memory");                           \
    } while (0)

    const int dc0 = g * 16;          // group g handles chunks dc0, dc0+32, ...
    ISSUE_CHUNK(dc0, 0);

    for (int c = 0; c < 16; c++) {
        const int b = c & 1;
        if (c < 15) {
            ISSUE_CHUNK(dc0 + (c + 1) * 32, b ^ 1);
            asm volatile("cp.async.wait_group 1;" ::: "memory");
        } else {
            asm volatile("cp.async.wait_group 0;" ::: "memory");
        }
        asm volatile("bar.sync %0, 128;" :: "r"(g + 1) : "memory");

        const float* An = sA[g][b][0];
        const float* Ap = sA[g][b][1];
        const float* Bn = sB[g][b][0];
        const float* Bq = sB[g][b][1];

#pragma unroll
        for (int dg = 0; dg < 16; dg += 4) {
            u64t bn[4], bq[4];
#pragma unroll
            for (int dd = 0; dd < 4; dd++) {
                bn[dd] = *(const u64t*)&Bn[(dg + dd) * 32 + j0];
                bq[dd] = *(const u64t*)&Bq[(dg + dd) * 32 + j0];
            }
#pragma unroll
            for (int x = 0; x < 4; x++) {
                const float4 av = *(const float4*)&An[(i0 + x) * SA_STRIDE + dg];
                const float4 pv = *(const float4*)&Ap[(i0 + x) * SA_STRIDE + dg];
                const u64t s0  = add2_(pk2(pv.x, pv.x), bq[0]);
                const u64t s1_ = add2_(pk2(pv.y, pv.y), bq[1]);
                const u64t s2_ = add2_(pk2(pv.z, pv.z), bq[2]);
                const u64t s3_ = add2_(pk2(pv.w, pv.w), bq[3]);
                const u64t df0 = add2_(pk2(av.x, av.x), bn[0]);   // a - b (b negated)
                const u64t df1 = add2_(pk2(av.y, av.y), bn[1]);
                const u64t df2 = add2_(pk2(av.z, av.z), bn[2]);
                const u64t df3 = add2_(pk2(av.w, av.w), bn[3]);
                const u64t sq0 = mul2_(df0, df0);
                const u64t sq1 = mul2_(df1, df1);
                const u64t sq2 = mul2_(df2, df2);
                const u64t sq3 = mul2_(df3, df3);
                d2a[x] = add2_(d2a[x], add2_(add2_(sq0, sq1), add2_(sq2, sq3)));
                // batched log + Montgomery batch inversion over 4 d's
                const u64t p01  = mul2_(s0, s1_);
                const u64t p012 = mul2_(p01, s2_);
                const u64t Pp   = mul2_(p012, s3_);
                float Pl, Ph; upk2(Pp, Pl, Ph);
                lda[x] = add2_(lda[x], pk2(lg2a(Pl), lg2a(Ph)));
                const u64t r2   = pk2(rcpa(Pl), rcpa(Ph));
                const u64t inv3 = mul2_(r2, p012);
                const u64t r3   = mul2_(r2, s3_);
                const u64t inv2 = mul2_(r3, p01);
                const u64t r23  = mul2_(r3, s2_);
                const u64t inv1 = mul2_(r23, s0);
                const u64t inv0 = mul2_(r23, s1_);
                t1a[x] = fma2_(sq0, inv0, t1a[x]);
                t1a[x] = fma2_(sq1, inv1, t1a[x]);
                t1a[x] = fma2_(sq2, inv2, t1a[x]);
                t1a[x] = fma2_(sq3, inv3, t1a[x]);
            }
        }
        asm volatile("bar.sync %0, 128;" :: "r"(g + 1) : "memory");
    }
#undef ISSUE_CHUNK

    // ---- combine group partials (overlay comb on sA; all compute is done) ----
    __syncthreads();
    u64t (*comb)[12] = (u64t (*)[12])&sA[0][0][0][0];
    if (g == 1) {
#pragma unroll
        for (int x = 0; x < 4; x++) {
            comb[t][3 * x]     = t1a[x];
            comb[t][3 * x + 1] = d2a[x];
            comb[t][3 * x + 2] = lda[x];
        }
    }
    __syncthreads();
    if (g == 0) {
#pragma unroll
        for (int x = 0; x < 4; x++) {
            t1a[x] = add2_(t1a[x], comb[t][3 * x]);
            d2a[x] = add2_(d2a[x], comb[t][3 * x + 1]);
            lda[x] = add2_(lda[x], comb[t][3 * x + 2]);
        }
        const int j = bj + j0;
        const float ld2A = g_ld2[j], ld2B = g_ld2[j + 1];
#pragma unroll
        for (int x = 0; x < 4; x++) {
            const int i = bi + i0 + x;
            const float ld1v = g_ld1[i];
            float tA, tB, dA, dB, lA, lB;
            upk2(t1a[x], tA, tB);
            upk2(d2a[x], dA, dB);
            upk2(lda[x], lA, lB);
            const float t2A = lA * (float)M_LN2 - 0.5f * (ld1v + ld2A);
            const float t2B = lB * (float)M_LN2 - 0.5f * (ld1v + ld2B);
            const float bdA = fmaf(0.125f, tA, 0.5f * t2A);
            const float bdB = fmaf(0.125f, tB, 0.5f * t2B);
            *(float2*)&g_sim[i * NB + j]  = make_float2(__expf(-bdA * (1.0f / ND)),
                                                        __expf(-bdB * (1.0f / ND)));
            *(float2*)&g_sim2[i * NB + j] = make_float2(__expf(-dA), __expf(-dB));
        }
    }
}

// ---------------- kernel 4: row LSE + col partials + fused final (last block) ----------------
__global__ void rowcol_kernel(const float* __restrict__ lsp, float* __restrict__ out)
{
    const float scale = lsp[0];
    const int t = threadIdx.x;
    const int lane = t & 31, w = t >> 5;

    if (blockIdx.x < NB) {
        __shared__ float shm[8], shm2[8], shs[8];
        __shared__ float s_diag, s_diag2, s_M, s_M2;
        const int i = blockIdx.x;
        const float* simr = g_sim + i * NB;
        const float* sim2r = g_sim2 + i * NB;

        const float l0 = scale * simr[t], l1 = scale * simr[t + 256];
        const float v0 = sim2r[t],        v1 = sim2r[t + 256];
        float m = fmaxf(l0, l1);
        float m2 = -1.0f;
        if (t == i)       { s_diag = l0; s_diag2 = v0; } else m2 = v0;
        if (t + 256 == i) { s_diag = l1; s_diag2 = v1; } else m2 = fmaxf(m2, v1);

        m = wmax(m); m2 = wmax(m2);
        if (!lane) { shm[w] = m; shm2[w] = m2; }
        __syncthreads();
        if (t == 0) {
            float M = shm[0], M2 = shm2[0];
            for (int k = 1; k < 8; k++) { M = fmaxf(M, shm[k]); M2 = fmaxf(M2, shm2[k]); }
            s_M = M; s_M2 = M2;
        }
        __syncthreads();
        const float M = s_M;
        float su = __expf(l0 - M) + __expf(l1 - M);
        su = wsum(su);
        if (!lane) shs[w] = su;
        __syncthreads();
        if (t == 0) {
            float S = 0.f;
            for (int k = 0; k < 8; k++) S += shs[k];
            g_lse_row[i] = M + __logf(S);
            g_diagl[i]   = s_diag;
            g_u[i]       = __expf(-s_diag2 / s_M2);
        }
    } else {
        __shared__ float sm[8][32], ssp[8][32];
        const int bid = blockIdx.x - NB;
        const int jg = bid & 15, rg = bid >> 4;      // 16 col-groups x 8 row-stripes
        const int x = t & 31, y = t >> 5;
        const int j = jg * 32 + x;
        const int r0 = rg * 64 + y * 8;
        float m = -1e30f, s = 0.0f;
#pragma unroll
        for (int k = 0; k < 8; k++) {
            const float l = scale * g_sim[(r0 + k) * NB + j];
            const float nm = fmaxf(m, l);
            s = s * __expf(m - nm) + __expf(l - nm);
            m = nm;
        }
        sm[y][x] = m; ssp[y][x] = s;
        __syncthreads();
        if (y == 0) {
            float M = m;
#pragma unroll
            for (int k = 1; k < 8; k++) M = fmaxf(M, sm[k][x]);
            float S = 0.f;
#pragma unroll
            for (int k = 0; k < 8; k++) S += ssp[k][x] * __expf(sm[k][x] - M);
            g_cm[rg * NB + j] = M;
            g_cs[rg * NB + j] = S;
        }
    }

    // ---- last-block final reduction ----
    __shared__ int s_last;
    __threadfence();
    __syncthreads();
    if (t == 0) s_last = (atomicAdd(&g_ctr, 1) == NB + 128 - 1);
    __syncthreads();
    if (!s_last) return;
    __threadfence();

    __shared__ float fsh[6][8];
    float acc[6] = {0.f, 0.f, 0.f, 0.f, 0.f, 0.f};
    for (int idx = t; idx < NB; idx += 256) {
        float M = -1e30f;
#pragma unroll
        for (int k = 0; k < 8; k++) M = fmaxf(M, g_cm[k * NB + idx]);
        float S = 0.f;
#pragma unroll
        for (int k = 0; k < 8; k++) S += g_cs[k * NB + idx] * __expf(g_cm[k * NB + idx] - M);
        const float lse_col = M + __logf(S);
        const float diag = g_diagl[idx];
        const float u = g_u[idx];
        const float as = 0.5f * (g_ms1[idx] + g_ms2[idx]);
        acc[0] += g_lse_row[idx] - diag;
        acc[1] += lse_col - diag;
        acc[2] += u;
        acc[3] += u * u;
        acc[4] += as * as;
        acc[5] += u * as;
    }
#pragma unroll
    for (int k = 0; k < 6; k++) {
        const float r = wsum(acc[k]);
        if (!lane) fsh[k][w] = r;
    }
    __syncthreads();
    if (t == 0) {
        float s[6];
        for (int k = 0; k < 6; k++) {
            float a = 0.f;
            for (int q = 0; q < 8; q++) a += fsh[k][q];
            s[k] = a;
        }
        const float loss_pro = 0.5f * ((s[0] + s[1]) * (1.0f / NB));
        const float cosv = s[5] / (fmaxf(sqrtf(s[3]), 1e-12f) * fmaxf(sqrtf(s[4]), 1e-12f));
        out[0] = loss_pro;
        out[1] = 2.4f * (1.0f - cosv);
        out[2] = 0.5f * (s[2] * (1.0f / NB));
    }
}

// ---------------- launch ----------------
extern "C" void kernel_launch(void* const* d_in, const int* in_sizes, int n_in,
                              void* d_out, int out_size)
{
    const float* mu1 = (const float*)d_in[0];
    const float* s1  = (const float*)d_in[1];
    const float* mu2 = (const float*)d_in[2];
    const float* s2  = (const float*)d_in[3];
    const float* ls  = (const float*)d_in[4];
    float* out = (float*)d_out;

    prep_kernel<<<2 * NB, 256>>>(mu1, s1, mu2, s2);
    tscale_kernel<<<dim3(16, 16), dim3(32, 8)>>>(mu2, s2);
    bd_kernel<<<dim3(NB / 32, NB / 32), 256>>>();
    rowcol_kernel<<<NB + 128, 256>>>(ls, out);
}

// round 9
// speedup vs baseline: 1.1760x; 1.0575x over previous
#include <cuda_runtime.h>
#include <math.h>

#define NB 512
#define ND 512
#define EPSF 1e-6f
#define HEPS (0.5f*1e-6f)

typedef unsigned long long u64t;

// ---------------- f32x2 packed helpers (sm_100a) ----------------
__device__ __forceinline__ u64t pk2(float lo, float hi){ u64t r; asm("mov.b64 %0, {%1,%2};" : "=l"(r) : "f"(lo), "f"(hi)); return r; }
__device__ __forceinline__ void upk2(u64t v, float&lo, float&hi){ asm("mov.b64 {%0,%1}, %2;" : "=f"(lo), "=f"(hi) : "l"(v)); }
__device__ __forceinline__ u64t fma2_(u64t a,u64t b,u64t c){ u64t d; asm("fma.rn.f32x2 %0,%1,%2,%3;" : "=l"(d) : "l"(a),"l"(b),"l"(c)); return d; }
__device__ __forceinline__ u64t mul2_(u64t a,u64t b){ u64t d; asm("mul.rn.f32x2 %0,%1,%2;" : "=l"(d) : "l"(a),"l"(b)); return d; }
__device__ __forceinline__ u64t add2_(u64t a,u64t b){ u64t d; asm("add.rn.f32x2 %0,%1,%2;" : "=l"(d) : "l"(a),"l"(b)); return d; }
__device__ __forceinline__ float rcpa(float x){ float r; asm("rcp.approx.f32 %0, %1;" : "=f"(r) : "f"(x)); return r; }
__device__ __forceinline__ float lg2a(float x){ float r; asm("lg2.approx.f32 %0, %1;" : "=f"(r) : "f"(x)); return r; }

// ---------------- scratch ----------------
__device__ float g_n1[NB * ND];    // normalized mu1, [i][d]
__device__ float g_h1[NB * ND];    // 0.5*sigma1 + HEPS, [i][d]
__device__ float g_n2t[NB * ND];   // NEGATED normalized mu2, TRANSPOSED [d][j]
__device__ float g_h2t[NB * ND];   // 0.5*sigma2 + HEPS, TRANSPOSED [d][j]
__device__ float g_ld1[NB], g_ld2[NB];
__device__ float g_ms1[NB], g_ms2[NB];
__device__ float g_inv2[NB];
// per-block partials: [chunk 0..15][row-or-col 0..511]
__device__ float g_rm[16 * NB], g_rs[16 * NB], g_dmin[16 * NB];
__device__ float g_cm[16 * NB], g_cs[16 * NB];
__device__ float g_dd[NB], g_diagl[NB];

// ---------------- reduction helpers ----------------
__device__ __forceinline__ float wsum(float v) {
#pragma unroll
    for (int o = 16; o; o >>= 1) v += __shfl_down_sync(0xffffffffu, v, o);
    return v;
}

// ---------------- kernel 1: per-row reductions + side-1 arrays ----------------
__global__ void prep_kernel(const float* __restrict__ mu1, const float* __restrict__ s1,
                            const float* __restrict__ mu2, const float* __restrict__ s2)
{
    __shared__ float sh[3][8];
    __shared__ float s_inv;
    const int row = blockIdx.x;
    const bool first = row < NB;
    const int r = first ? row : row - NB;
    const float* mu = (first ? mu1 : mu2) + r * ND;
    const float* sg = (first ? s1 : s2) + r * ND;
    const int t = threadIdx.x;

    float ssq = 0.f, lsum = 0.f, msum = 0.f;
    for (int c = t; c < ND; c += 256) {
        float x = mu[c];
        ssq += x * x;
        float sv = sg[c];
        lsum += __logf(sv + EPSF);
        msum += sv;
        if (first) g_h1[r * ND + c] = fmaf(0.5f, sv, HEPS);
    }
    ssq = wsum(ssq); lsum = wsum(lsum); msum = wsum(msum);
    const int lane = t & 31, w = t >> 5;
    if (!lane) { sh[0][w] = ssq; sh[1][w] = lsum; sh[2][w] = msum; }
    __syncthreads();
    if (t == 0) {
        float a = 0.f, b = 0.f, c2 = 0.f;
        for (int k = 0; k < 8; k++) { a += sh[0][k]; b += sh[1][k]; c2 += sh[2][k]; }
        float inv = 1.0f / fmaxf(sqrtf(a), 1e-12f);
        s_inv = inv;
        (first ? g_ld1 : g_ld2)[r] = b;
        (first ? g_ms1 : g_ms2)[r] = c2 * (1.0f / ND);
        if (!first) g_inv2[r] = -inv;
    }
    __syncthreads();
    if (first) {
        const float inv = s_inv;
        for (int c = t; c < ND; c += 256) g_n1[r * ND + c] = mu[c] * inv;
    }
}

// ---------------- kernel 2: transpose + scale side-2 arrays ----------------
__global__ void tscale_kernel(const float* __restrict__ mu2, const float* __restrict__ s2)
{
    __shared__ float tn[32][33], th[32][33];
    const int bx = blockIdx.x * 32;   // d origin
    const int by = blockIdx.y * 32;   // j origin
    const int tx = threadIdx.x, ty = threadIdx.y;   // 32 x 8
#pragma unroll
    for (int k = 0; k < 4; k++) {
        const int j = by + ty + k * 8;
        const float iv = g_inv2[j];
        tn[ty + k * 8][tx] = mu2[j * ND + bx + tx] * iv;
        th[ty + k * 8][tx] = fmaf(0.5f, s2[j * ND + bx + tx], HEPS);
    }
    __syncthreads();
#pragma unroll
    for (int k = 0; k < 4; k++) {
        const int d = bx + ty + k * 8;
        g_n2t[d * NB + by + tx] = tn[tx][ty + k * 8];
        g_h2t[d * NB + by + tx] = th[tx][ty + k * 8];
    }
}

// ---------------- kernel 3: Bhattacharyya O(B^2 D) pass + fused partials ----------------
// 32x32 tile, 256 threads = 2 anti-phase groups of 128 (warps 0-3 / 4-7) splitting D.
// smem pool layout (floats):
//   A: [grp][arr][i][36]  at g*2304 + arr*1152        (4608 floats)
//   B: [grp][arr][d][32]  at 4608 + g*2048 + arr*1024 (4096 floats)
#define SN1(gg,i,d) pool[(gg)*2304 + (i)*36 + (d)]
#define SS1(gg,i,d) pool[(gg)*2304 + 1152 + (i)*36 + (d)]
#define SN2(gg,d,j) pool[4608 + (gg)*2048 + (d)*32 + (j)]
#define SS2(gg,d,j) pool[4608 + (gg)*2048 + 1024 + (d)*32 + (j)]

__global__ void __launch_bounds__(256, 2) bd_kernel(const float* __restrict__ lsp)
{
    __shared__ __align__(16) float pool[8704];

    const int bi = blockIdx.y * 32, bj = blockIdx.x * 32;
    const int tid = threadIdx.x;
    const int g  = tid >> 7;          // group (warps 0-3 vs 4-7)
    const int t  = tid & 127;
    const int tx = t & 15, ty = t >> 4;
    const int i0 = 4 * ty, j0 = 2 * tx;

    u64t t1a[4], d2a[4], lda[4];
#pragma unroll
    for (int x = 0; x < 4; x++) { t1a[x] = 0ull; d2a[x] = 0ull; lda[x] = 0ull; }

    for (int c = 0; c < 8; c++) {
        const int dc = g * 32 + c * 64;
        // loader: 2 x float4 per array per thread (32 rows x 8 segs)
#pragma unroll
        for (int k = 0; k < 2; k++) {
            const int s = t + k * 128;
            const int r = s >> 3, c4 = (s & 7) * 4;
            *(float4*)&SN1(g, r, c4) = *(const float4*)&g_n1[(bi + r) * ND + dc + c4];
            *(float4*)&SS1(g, r, c4) = *(const float4*)&g_h1[(bi + r) * ND + dc + c4];
            *(float4*)&SN2(g, r, c4) = *(const float4*)&g_n2t[(dc + r) * NB + bj + c4];
            *(float4*)&SS2(g, r, c4) = *(const float4*)&g_h2t[(dc + r) * NB + bj + c4];
        }
        asm volatile("bar.sync %0, 128;" :: "r"(g + 1) : "memory");

#pragma unroll 2
        for (int dg = 0; dg < 32; dg += 4) {
            u64t bn[4], bq[4];
#pragma unroll
            for (int dd = 0; dd < 4; dd++) {
                bn[dd] = *(const u64t*)&SN2(g, dg + dd, j0);
                bq[dd] = *(const u64t*)&SS2(g, dg + dd, j0);
            }
#pragma unroll
            for (int x = 0; x < 4; x++) {
                const float4 av = *(const float4*)&SN1(g, i0 + x, dg);
                const float4 pv = *(const float4*)&SS1(g, i0 + x, dg);
                const u64t s0  = add2_(pk2(pv.x, pv.x), bq[0]);
                const u64t s1_ = add2_(pk2(pv.y, pv.y), bq[1]);
                const u64t s2_ = add2_(pk2(pv.z, pv.z), bq[2]);
                const u64t s3_ = add2_(pk2(pv.w, pv.w), bq[3]);
                const u64t df0 = add2_(pk2(av.x, av.x), bn[0]);   // a - b (b negated)
                const u64t df1 = add2_(pk2(av.y, av.y), bn[1]);
                const u64t df2 = add2_(pk2(av.z, av.z), bn[2]);
                const u64t df3 = add2_(pk2(av.w, av.w), bn[3]);
                const u64t sq0 = mul2_(df0, df0);
                const u64t sq1 = mul2_(df1, df1);
                const u64t sq2 = mul2_(df2, df2);
                const u64t sq3 = mul2_(df3, df3);
                d2a[x] = add2_(d2a[x], add2_(add2_(sq0, sq1), add2_(sq2, sq3)));
                // numerator-pair Montgomery: sum sq_d/s_d = N/P, one rcp per 4 d's
                const u64t p01 = mul2_(s0, s1_);
                const u64t p23 = mul2_(s2_, s3_);
                const u64t P   = mul2_(p01, p23);
                float Pl, Ph; upk2(P, Pl, Ph);
                lda[x] = add2_(lda[x], pk2(lg2a(Pl), lg2a(Ph)));
                const u64t rP  = pk2(rcpa(Pl), rcpa(Ph));
                u64t N01 = mul2_(sq0, s1_); N01 = fma2_(sq1, s0,  N01);
                u64t N23 = mul2_(sq2, s3_); N23 = fma2_(sq3, s2_, N23);
                u64t N   = mul2_(N01, p23); N   = fma2_(N23, p01, N);
                t1a[x] = fma2_(N, rP, t1a[x]);
            }
        }
        asm volatile("bar.sync %0, 128;" :: "r"(g + 1) : "memory");
    }

    // ---- combine group partials ----
    __syncthreads();
    u64t (*comb)[12] = (u64t (*)[12])&pool[0];
    if (g == 1) {
#pragma unroll
        for (int x = 0; x < 4; x++) {
            comb[t][3 * x]     = t1a[x];
            comb[t][3 * x + 1] = d2a[x];
            comb[t][3 * x + 2] = lda[x];
        }
    }
    __syncthreads();
    if (g == 1) return;

    // ---- group 0: epilogue (sim, logits, fused row/col partials) ----
#pragma unroll
    for (int x = 0; x < 4; x++) {
        t1a[x] = add2_(t1a[x], comb[t][3 * x]);
        d2a[x] = add2_(d2a[x], comb[t][3 * x + 1]);
        lda[x] = add2_(lda[x], comb[t][3 * x + 2]);
    }
    const float scale = lsp[0];
    const int j = bj + j0;
    const float ld2A = g_ld2[j], ld2B = g_ld2[j + 1];
    float lv[4][2], dv[4][2];
#pragma unroll
    for (int x = 0; x < 4; x++) {
        const int i = bi + i0 + x;
        const float ld1v = g_ld1[i];
        float tA, tB, dA, dB, lA, lB;
        upk2(t1a[x], tA, tB);
        upk2(d2a[x], dA, dB);
        upk2(lda[x], lA, lB);
        const float t2A = lA * (float)M_LN2 - 0.5f * (ld1v + ld2A);
        const float t2B = lB * (float)M_LN2 - 0.5f * (ld1v + ld2B);
        const float bdA = fmaf(0.125f, tA, 0.5f * t2A);
        const float bdB = fmaf(0.125f, tB, 0.5f * t2B);
        lv[x][0] = scale * __expf(-bdA * (1.0f / ND));
        lv[x][1] = scale * __expf(-bdB * (1.0f / ND));
        dv[x][0] = dA;
        dv[x][1] = dB;
    }

    // row partials: reduce over the 16 tx lanes (half-warp xor shuffles)
    const int bjG = blockIdx.x, biG = blockIdx.y;
#pragma unroll
    for (int x = 0; x < 4; x++) {
        const int i = bi + i0 + x;
        float rm = fmaxf(lv[x][0], lv[x][1]);
#pragma unroll
        for (int off = 8; off; off >>= 1) rm = fmaxf(rm, __shfl_xor_sync(0xffffffffu, rm, off));
        float rs = __expf(lv[x][0] - rm) + __expf(lv[x][1] - rm);
#pragma unroll
        for (int off = 8; off; off >>= 1) rs += __shfl_xor_sync(0xffffffffu, rs, off);
        float mA = (j == i)     ? 1e30f : dv[x][0];
        float mB = (j + 1 == i) ? 1e30f : dv[x][1];
        float dm = fminf(mA, mB);
#pragma unroll
        for (int off = 8; off; off >>= 1) dm = fminf(dm, __shfl_xor_sync(0xffffffffu, dm, off));
        if (tx == 0) {
            g_rm[bjG * NB + i]   = rm;
            g_rs[bjG * NB + i]   = rs;
            g_dmin[bjG * NB + i] = dm;
        }
        if (j == i)     { g_dd[i] = dv[x][0]; g_diagl[i] = lv[x][0]; }
        if (j + 1 == i) { g_dd[i] = dv[x][1]; g_diagl[i] = lv[x][1]; }
    }

    // col partials: per-thread over 4 i's, merge ty-pair via xor-16, then 4 warps via smem
    float* scm = &pool[4608];          // [4][32]
    float* scs = &pool[4608 + 128];
    const int w = t >> 5;
#pragma unroll
    for (int jj = 0; jj < 2; jj++) {
        float cm = fmaxf(fmaxf(lv[0][jj], lv[1][jj]), fmaxf(lv[2][jj], lv[3][jj]));
        float cs = __expf(lv[0][jj] - cm) + __expf(lv[1][jj] - cm)
                 + __expf(lv[2][jj] - cm) + __expf(lv[3][jj] - cm);
        const float om = __shfl_xor_sync(0xffffffffu, cm, 16);
        const float os = __shfl_xor_sync(0xffffffffu, cs, 16);
        const float nm = fmaxf(cm, om);
        cs = cs * __expf(cm - nm) + os * __expf(om - nm);
        cm = nm;
        if ((t & 31) < 16) { scm[w * 32 + j0 + jj] = cm; scs[w * 32 + j0 + jj] = cs; }
    }
    asm volatile("bar.sync 1, 128;" ::: "memory");
    if (t < 32) {
        float m = scm[t], s = scs[t];
#pragma unroll
        for (int k = 1; k < 4; k++) {
            const float om = scm[k * 32 + t], os = scs[k * 32 + t];
            const float nm = fmaxf(m, om);
            s = s * __expf(m - nm) + os * __expf(om - nm);
            m = nm;
        }
        g_cm[biG * NB + bj + t] = m;
        g_cs[biG * NB + bj + t] = s;
    }
}

// ---------------- kernel 4: final — combine 16 partials per row/col + losses ----------------
__global__ void final_kernel(float* __restrict__ out)
{
    __shared__ float fsh[6][16];
    const int t = threadIdx.x;   // 512 threads

    float M = -1e30f;
#pragma unroll
    for (int k = 0; k < 16; k++) M = fmaxf(M, g_rm[k * NB + t]);
    float S = 0.f;
#pragma unroll
    for (int k = 0; k < 16; k++) S += g_rs[k * NB + t] * __expf(g_rm[k * NB + t] - M);
    const float lse_row = M + __logf(S);

    float Mc = -1e30f;
#pragma unroll
    for (int k = 0; k < 16; k++) Mc = fmaxf(Mc, g_cm[k * NB + t]);
    float Sc = 0.f;
#pragma unroll
    for (int k = 0; k < 16; k++) Sc += g_cs[k * NB + t] * __expf(g_cm[k * NB + t] - Mc);
    const float lse_col = Mc + __logf(Sc);

    float dmin = 1e30f;
#pragma unroll
    for (int k = 0; k < 16; k++) dmin = fminf(dmin, g_dmin[k * NB + t]);
    const float u = __expf(-__expf(dmin - g_dd[t]));   // exp(-diag_sim2/negmax)

    const float diag = g_diagl[t];
    const float as = 0.5f * (g_ms1[t] + g_ms2[t]);
    float v[6] = { lse_row - diag, lse_col - diag, u, u * u, as * as, u * as };
    const int lane = t & 31, w = t >> 5;
#pragma unroll
    for (int k = 0; k < 6; k++) {
        const float r = wsum(v[k]);
        if (!lane) fsh[k][w] = r;
    }
    __syncthreads();
    if (t == 0) {
        float s[6];
        for (int k = 0; k < 6; k++) {
            float a = 0.f;
            for (int q = 0; q < 16; q++) a += fsh[k][q];
            s[k] = a;
        }
        const float loss_pro = 0.5f * ((s[0] + s[1]) * (1.0f / NB));
        const float cosv = s[5] / (fmaxf(sqrtf(s[3]), 1e-12f) * fmaxf(sqrtf(s[4]), 1e-12f));
        out[0] = loss_pro;
        out[1] = 2.4f * (1.0f - cosv);
        out[2] = 0.5f * (s[2] * (1.0f / NB));
    }
}

// ---------------- launch ----------------
extern "C" void kernel_launch(void* const* d_in, const int* in_sizes, int n_in,
                              void* d_out, int out_size)
{
    const float* mu1 = (const float*)d_in[0];
    const float* s1  = (const float*)d_in[1];
    const float* mu2 = (const float*)d_in[2];
    const float* s2  = (const float*)d_in[3];
    const float* ls  = (const float*)d_in[4];
    float* out = (float*)d_out;

    prep_kernel<<<2 * NB, 256>>>(mu1, s1, mu2, s2);
    tscale_kernel<<<dim3(16, 16), dim3(32, 8)>>>(mu2, s2);
    bd_kernel<<<dim3(NB / 32, NB / 32), 256>>>(ls);
    final_kernel<<<1, NB>>>(out);
}